// round 2
// baseline (speedup 1.0000x reference)
#include <cuda_runtime.h>
#include <cstdint>

// Problem shape (fixed by setup_inputs): x [4,2048,4096] f32,
// W [4096,4096] int8 in reference but delivered as int32 by the harness
// (harness supports f32/i32/bf16 only), wscale [4096] f32, bias [4096] f32.
// T = 8192 tokens.
#define D_IN  4096
#define D_OUT 4096
#define MAX_T 8192

// Scratch (allocation-free rule: __device__ globals)
__device__ int8_t g_xq[(size_t)MAX_T * D_IN];      // quantized activations
__device__ float  g_xscale[MAX_T];                 // per-token scale
__device__ int8_t g_wq[(size_t)D_OUT * D_IN];      // repacked int8 weights

// ---------------------------------------------------------------------------
// Kernel 0: repack weights int32 -> int8 (harness delivers jnp.int8 as int32).
// Each thread packs 4 int32 into one 4-byte word. 4096*4096/4 = 4.19M words.
// ---------------------------------------------------------------------------
__global__ __launch_bounds__(256) void pack_w_kernel(const int* __restrict__ w32)
{
    const size_t i = (size_t)blockIdx.x * blockDim.x + threadIdx.x;   // word idx
    const size_t nwords = (size_t)D_OUT * D_IN / 4;
    if (i >= nwords) return;
    const int4 v = reinterpret_cast<const int4*>(w32)[i];
    int packed = (v.x & 0xFF) | ((v.y & 0xFF) << 8) |
                 ((v.z & 0xFF) << 16) | ((v.w & 0xFF) << 24);
    reinterpret_cast<int*>(g_wq)[i] = packed;
}

// ---------------------------------------------------------------------------
// Kernel 1: dynamic per-token symmetric int8 quantization.
// One CTA per token (row of 4096 floats), 256 threads.
// ---------------------------------------------------------------------------
__global__ __launch_bounds__(256) void quant_kernel(const float* __restrict__ x)
{
    const int t = blockIdx.x;
    const float4* __restrict__ xr =
        reinterpret_cast<const float4*>(x + (size_t)t * D_IN);

    // Each thread loads 4 float4 (16 floats); 256 * 16 = 4096.
    float4 v[4];
    float amax = 0.0f;
#pragma unroll
    for (int i = 0; i < 4; i++) {
        v[i] = xr[threadIdx.x + i * 256];
        amax = fmaxf(amax, fmaxf(fmaxf(fabsf(v[i].x), fabsf(v[i].y)),
                                 fmaxf(fabsf(v[i].z), fabsf(v[i].w))));
    }

    // Block max reduction
    __shared__ float red[8];
#pragma unroll
    for (int o = 16; o > 0; o >>= 1)
        amax = fmaxf(amax, __shfl_xor_sync(0xffffffffu, amax, o));
    if ((threadIdx.x & 31) == 0) red[threadIdx.x >> 5] = amax;
    __syncthreads();
    float m = red[0];
#pragma unroll
    for (int w = 1; w < 8; w++) m = fmaxf(m, red[w]);

    const float scale = fmaxf(m, 1e-8f) / 127.0f;
    if (threadIdx.x == 0) g_xscale[t] = scale;

    // Quantize: round-to-nearest-even (rintf matches jnp.round), clip [-128,127]
    int* __restrict__ outw = reinterpret_cast<int*>(g_xq + (size_t)t * D_IN);
#pragma unroll
    for (int i = 0; i < 4; i++) {
        int q0 = (int)fminf(fmaxf(rintf(v[i].x / scale), -128.0f), 127.0f);
        int q1 = (int)fminf(fmaxf(rintf(v[i].y / scale), -128.0f), 127.0f);
        int q2 = (int)fminf(fmaxf(rintf(v[i].z / scale), -128.0f), 127.0f);
        int q3 = (int)fminf(fmaxf(rintf(v[i].w / scale), -128.0f), 127.0f);
        int packed = (q0 & 0xFF) | ((q1 & 0xFF) << 8) |
                     ((q2 & 0xFF) << 16) | ((q3 & 0xFF) << 24);
        outw[threadIdx.x + i * 256] = packed;
    }
}

// ---------------------------------------------------------------------------
// Kernel 2: int8 GEMM C[T, D_OUT] = xq @ W^T with fused dequant epilogue.
// Tile: BM=128, BN=128, BK=64. 256 threads, 8x8 micro-tile per thread, dp4a.
// Shared tiles stored kw4-major ([4][128] int4) for conflict-free LDS.128.
// ---------------------------------------------------------------------------
#define BM 128
#define BN 128
#define BK 64

__global__ __launch_bounds__(256) void gemm_kernel(
    const float*  __restrict__ wscale,
    const float*  __restrict__ bias,
    float*        __restrict__ out)
{
    __shared__ int4 As4[4][BM];   // [kw4][m-row], each int4 = 16 int8 of k
    __shared__ int4 Bs4[4][BN];   // [kw4][n-row]

    const int tid = threadIdx.x;
    const int tx  = tid & 15;     // 0..15 -> output column group
    const int ty  = tid >> 4;     // 0..15 -> output row group
    const int m0  = blockIdx.y * BM;
    const int n0  = blockIdx.x * BN;

    const int4* __restrict__ Ag = reinterpret_cast<const int4*>(g_xq);
    const int4* __restrict__ Bg = reinterpret_cast<const int4*>(g_wq);
    const int row_i4 = D_IN / 16;   // 256 int4 per row

    int acc[8][8];
#pragma unroll
    for (int i = 0; i < 8; i++)
#pragma unroll
        for (int j = 0; j < 8; j++) acc[i][j] = 0;

    for (int kb = 0; kb < D_IN / BK; kb++) {
        // Load A/B tiles: 512 int4 each (2 x 256-thread passes).
#pragma unroll
        for (int l = 0; l < 2; l++) {
            int idx  = l * 256 + tid;       // 0..511
            int row  = idx >> 2;            // 0..127
            int kw4  = idx & 3;             // 0..3
            As4[kw4][row] = Ag[(size_t)(m0 + row) * row_i4 + kb * 4 + kw4];
            Bs4[kw4][row] = Bg[(size_t)(n0 + row) * row_i4 + kb * 4 + kw4];
        }
        __syncthreads();

#pragma unroll
        for (int kw4 = 0; kw4 < 4; kw4++) {
            int4 a[8], b[8];
#pragma unroll
            for (int i = 0; i < 8; i++) a[i] = As4[kw4][ty * 8 + i];
#pragma unroll
            for (int j = 0; j < 8; j++) b[j] = Bs4[kw4][j * 16 + tx];
#pragma unroll
            for (int i = 0; i < 8; i++) {
#pragma unroll
                for (int j = 0; j < 8; j++) {
                    acc[i][j] = __dp4a(a[i].x, b[j].x, acc[i][j]);
                    acc[i][j] = __dp4a(a[i].y, b[j].y, acc[i][j]);
                    acc[i][j] = __dp4a(a[i].z, b[j].z, acc[i][j]);
                    acc[i][j] = __dp4a(a[i].w, b[j].w, acc[i][j]);
                }
            }
        }
        __syncthreads();
    }

    // Fused dequant + bias epilogue. Columns n0 + j*16 + tx -> lanes write
    // consecutive floats (coalesced).
#pragma unroll
    for (int i = 0; i < 8; i++) {
        const int m = m0 + ty * 8 + i;
        const float xs = g_xscale[m];
        float* __restrict__ orow = out + (size_t)m * D_OUT;
#pragma unroll
        for (int j = 0; j < 8; j++) {
            const int n = n0 + j * 16 + tx;
            orow[n] = (float)acc[i][j] * xs * wscale[n] + bias[n];
        }
    }
}

// ---------------------------------------------------------------------------
extern "C" void kernel_launch(void* const* d_in, const int* in_sizes, int n_in,
                              void* d_out, int out_size)
{
    const float* x      = (const float*)d_in[0];
    const int*   w32    = (const int*)d_in[1];     // int8 promoted to int32
    const float* wscale = (const float*)d_in[2];
    const float* bias   = (const float*)d_in[3];
    float*       out    = (float*)d_out;

    const int T = in_sizes[0] / D_IN;   // 8192

    const size_t nwords = (size_t)D_OUT * D_IN / 4;
    pack_w_kernel<<<(int)((nwords + 255) / 256), 256>>>(w32);

    quant_kernel<<<T, 256>>>(x);

    dim3 grid(D_OUT / BN, T / BM);      // (32, 64)
    gemm_kernel<<<grid, 256>>>(wscale, bias, out);
}

// round 4
// speedup vs baseline: 1.3099x; 1.3099x over previous
#include <cuda_runtime.h>
#include <cstdint>

// Shapes fixed by setup_inputs: x [4,2048,4096] f32, W [4096,4096] int8
// (delivered by harness as int32), wscale [4096] f32, bias [4096] f32.
#define D_IN  4096
#define D_OUT 4096
#define MAX_T 8192

// Scratch (allocation-free rule: __device__ globals)
__device__ int8_t g_xq[(size_t)MAX_T * D_IN];
__device__ float  g_xscale[MAX_T];
__device__ int8_t g_wq[(size_t)D_OUT * D_IN];

// ===========================================================================
// Helpers
// ===========================================================================
__device__ __forceinline__ uint32_t smem_u32(const void* p) {
    uint32_t a;
    asm("{ .reg .u64 t; cvta.to.shared.u64 t, %1; cvt.u32.u64 %0, t; }"
        : "=r"(a) : "l"(p));
    return a;
}
__device__ __forceinline__ uint32_t lds32(uint32_t addr) {
    uint32_t v;
    asm volatile("ld.shared.b32 %0, [%1];" : "=r"(v) : "r"(addr));
    return v;
}
#define CP_ASYNC16(dst, src) \
    asm volatile("cp.async.cg.shared.global [%0], [%1], 16;" \
                 :: "r"(dst), "l"(src) : "memory")
#define CP_COMMIT() asm volatile("cp.async.commit_group;" ::: "memory")
#define CP_WAIT(n)  asm volatile("cp.async.wait_group %0;" :: "n"(n) : "memory")
#define CP_WAIT_ALL() asm volatile("cp.async.wait_all;" ::: "memory")

// int8 tensor-core MMA (sm_80 baseline): D[16x8]s32 += A[16x32]s8 row * B[32x8]s8 col
__device__ __forceinline__ void mma_i8(int* c, const uint32_t* a, const uint32_t* b) {
    asm volatile(
        "mma.sync.aligned.m16n8k32.row.col.s32.s8.s8.s32 "
        "{%0,%1,%2,%3}, {%4,%5,%6,%7}, {%8,%9}, {%0,%1,%2,%3};"
        : "+r"(c[0]), "+r"(c[1]), "+r"(c[2]), "+r"(c[3])
        : "r"(a[0]), "r"(a[1]), "r"(a[2]), "r"(a[3]), "r"(b[0]), "r"(b[1]));
}

// ===========================================================================
// Kernel 0: repack weights int32 -> int8
// ===========================================================================
__global__ __launch_bounds__(256) void pack_w_kernel(const int* __restrict__ w32)
{
    const size_t i = (size_t)blockIdx.x * blockDim.x + threadIdx.x;
    const size_t nwords = (size_t)D_OUT * D_IN / 4;
    if (i >= nwords) return;
    const int4 v = reinterpret_cast<const int4*>(w32)[i];
    reinterpret_cast<int*>(g_wq)[i] =
        (v.x & 0xFF) | ((v.y & 0xFF) << 8) | ((v.z & 0xFF) << 16) | ((v.w & 0xFF) << 24);
}

// ===========================================================================
// Kernel 1: dynamic per-token int8 quantization (one CTA / token)
// ===========================================================================
__global__ __launch_bounds__(256) void quant_kernel(const float* __restrict__ x)
{
    const int t = blockIdx.x;
    const float4* __restrict__ xr = reinterpret_cast<const float4*>(x + (size_t)t * D_IN);

    float4 v[4];
    float amax = 0.0f;
#pragma unroll
    for (int i = 0; i < 4; i++) {
        v[i] = xr[threadIdx.x + i * 256];
        amax = fmaxf(amax, fmaxf(fmaxf(fabsf(v[i].x), fabsf(v[i].y)),
                                 fmaxf(fabsf(v[i].z), fabsf(v[i].w))));
    }
    __shared__ float red[8];
#pragma unroll
    for (int o = 16; o > 0; o >>= 1)
        amax = fmaxf(amax, __shfl_xor_sync(0xffffffffu, amax, o));
    if ((threadIdx.x & 31) == 0) red[threadIdx.x >> 5] = amax;
    __syncthreads();
    float m = red[0];
#pragma unroll
    for (int w = 1; w < 8; w++) m = fmaxf(m, red[w]);

    const float scale = fmaxf(m, 1e-8f) / 127.0f;
    if (threadIdx.x == 0) g_xscale[t] = scale;

    int* __restrict__ outw = reinterpret_cast<int*>(g_xq + (size_t)t * D_IN);
#pragma unroll
    for (int i = 0; i < 4; i++) {
        int q0 = (int)fminf(fmaxf(rintf(v[i].x / scale), -128.0f), 127.0f);
        int q1 = (int)fminf(fmaxf(rintf(v[i].y / scale), -128.0f), 127.0f);
        int q2 = (int)fminf(fmaxf(rintf(v[i].z / scale), -128.0f), 127.0f);
        int q3 = (int)fminf(fmaxf(rintf(v[i].w / scale), -128.0f), 127.0f);
        outw[threadIdx.x + i * 256] = (q0 & 0xFF) | ((q1 & 0xFF) << 8) |
                                      ((q2 & 0xFF) << 16) | ((q3 & 0xFF) << 24);
    }
}

// ===========================================================================
// Kernel 2: int8 GEMM via mma.sync.m16n8k32 (sm_80 path; tcgen05 is not
// available through this harness's PTX target sm_103).
// CTA tile 128x128x64, 3-stage cp.async pipeline, 256 threads.
// Warp grid 4(M) x 2(N); warp tile 32x64; acc[2][8][4] s32 per thread.
// SMEM rows padded to 80B so fragment LDS.32 loads are bank-conflict-free:
// bank(row,quad) = (20*row + quad) % 32, 20g%32 distinct for g=0..7.
// ===========================================================================
#define BM 128
#define BN 128
#define BK 64
#define STAGES 3
#define NKB (D_IN / BK)          // 64
#define ROW_B 80                 // padded row stride in bytes
#define A_TILE (BM * ROW_B)      // 10240
#define B_TILE (BN * ROW_B)      // 10240
#define STAGE_B (A_TILE + B_TILE)            // 20480
#define SMEM_TOTAL (STAGES * STAGE_B)        // 61440

__global__ __launch_bounds__(256) void gemm_i8_kernel(
    const float* __restrict__ wscale,
    const float* __restrict__ bias,
    float* __restrict__ out)
{
    extern __shared__ char smem[];
    const uint32_t sbase = smem_u32(smem);

    const int tid  = threadIdx.x;
    const int wid  = tid >> 5;
    const int lane = tid & 31;
    const int g    = lane >> 2;      // group 0..7
    const int tq   = lane & 3;       // quad 0..3
    const int wm   = wid & 3;        // warp M index (0..3)
    const int wn   = wid >> 2;       // warp N index (0..1)

    const int m0 = blockIdx.y * BM;
    const int n0 = blockIdx.x * BN;

    // per-thread cp.async mapping: 1024 16B-chunks per stage (A 512 + B 512),
    // 4 chunks per thread. row = idx/4, c16 = idx%4.
    const int ldrow = tid >> 2;      // 0..63
    const int ldc   = tid & 3;       // 0..3

    int acc[2][8][4];
#pragma unroll
    for (int mt = 0; mt < 2; mt++)
#pragma unroll
        for (int nt = 0; nt < 8; nt++)
#pragma unroll
            for (int r = 0; r < 4; r++) acc[mt][nt][r] = 0;

    // ---- stage loader ----
    auto load_stage = [&](int s, int kb) {
        const uint32_t sa = sbase + s * STAGE_B;
        const uint32_t sb = sa + A_TILE;
        const size_t kcol = (size_t)kb * BK + ldc * 16;
        // A: rows ldrow and ldrow+64
#pragma unroll
        for (int h = 0; h < 2; h++) {
            const int row = ldrow + h * 64;
            CP_ASYNC16(sa + row * ROW_B + ldc * 16,
                       g_xq + (size_t)(m0 + row) * D_IN + kcol);
        }
        // B: rows ldrow and ldrow+64
#pragma unroll
        for (int h = 0; h < 2; h++) {
            const int row = ldrow + h * 64;
            CP_ASYNC16(sb + row * ROW_B + ldc * 16,
                       g_wq + (size_t)(n0 + row) * D_IN + kcol);
        }
    };

    // ---- prologue: fill STAGES-1 stages ----
#pragma unroll
    for (int s = 0; s < STAGES - 1; s++) {
        load_stage(s, s);
        CP_COMMIT();
    }

    // per-thread fragment base addresses (stage-relative)
    const uint32_t a_off = (uint32_t)((wm * 32 + g) * ROW_B + tq * 4);
    const uint32_t b_off = (uint32_t)(A_TILE + (wn * 64 + g) * ROW_B + tq * 4);

    // ---- main loop ----
    for (int kb = 0; kb < NKB; kb++) {
        CP_WAIT(STAGES - 2);
        __syncthreads();

        // prefetch next stage (overwrites stage consumed 2 iters ago)
        const int pf = kb + STAGES - 1;
        if (pf < NKB) load_stage(pf % STAGES, pf);
        CP_COMMIT();

        const uint32_t st = sbase + (kb % STAGES) * STAGE_B;
        const uint32_t ab = st + a_off;
        const uint32_t bb = st + b_off;

#pragma unroll
        for (int ks = 0; ks < 2; ks++) {          // two K=32 steps per BK=64
            uint32_t af[2][4];
#pragma unroll
            for (int mt = 0; mt < 2; mt++) {
                const uint32_t base = ab + mt * (16 * ROW_B) + ks * 32;
                af[mt][0] = lds32(base);
                af[mt][1] = lds32(base + 8 * ROW_B);
                af[mt][2] = lds32(base + 16);
                af[mt][3] = lds32(base + 8 * ROW_B + 16);
            }
            uint32_t bf[8][2];
#pragma unroll
            for (int nt = 0; nt < 8; nt++) {
                const uint32_t base = bb + nt * (8 * ROW_B) + ks * 32;
                bf[nt][0] = lds32(base);
                bf[nt][1] = lds32(base + 16);
            }
#pragma unroll
            for (int mt = 0; mt < 2; mt++)
#pragma unroll
                for (int nt = 0; nt < 8; nt++)
                    mma_i8(acc[mt][nt], af[mt], bf[nt]);
        }
        __syncthreads();
    }

    // ---- epilogue: stage wscale/bias in smem, fused dequant, float2 stores
    CP_WAIT_ALL();
    __syncthreads();
    float* ws_s = reinterpret_cast<float*>(smem);          // 128 floats
    float* bs_s = ws_s + BN;                                // 128 floats
    if (tid < BN) {
        ws_s[tid] = wscale[n0 + tid];
        bs_s[tid] = bias[n0 + tid];
    }
    __syncthreads();

#pragma unroll
    for (int mt = 0; mt < 2; mt++) {
        const int row0 = m0 + wm * 32 + mt * 16 + g;
        const float xs0 = g_xscale[row0];
        const float xs1 = g_xscale[row0 + 8];
        float* __restrict__ o0 = out + (size_t)row0 * D_OUT;
        float* __restrict__ o1 = out + (size_t)(row0 + 8) * D_OUT;
#pragma unroll
        for (int nt = 0; nt < 8; nt++) {
            const int nl = wn * 64 + nt * 8 + tq * 2;      // CTA-local col
            const float w0 = ws_s[nl], w1 = ws_s[nl + 1];
            const float b0 = bs_s[nl], b1 = bs_s[nl + 1];
            float2 v0, v1;
            v0.x = (float)acc[mt][nt][0] * xs0 * w0 + b0;
            v0.y = (float)acc[mt][nt][1] * xs0 * w1 + b1;
            v1.x = (float)acc[mt][nt][2] * xs1 * w0 + b0;
            v1.y = (float)acc[mt][nt][3] * xs1 * w1 + b1;
            *reinterpret_cast<float2*>(o0 + n0 + nl) = v0;
            *reinterpret_cast<float2*>(o1 + n0 + nl) = v1;
        }
    }
}

// ===========================================================================
extern "C" void kernel_launch(void* const* d_in, const int* in_sizes, int n_in,
                              void* d_out, int out_size)
{
    const float* x      = (const float*)d_in[0];
    const int*   w32    = (const int*)d_in[1];
    const float* wscale = (const float*)d_in[2];
    const float* bias   = (const float*)d_in[3];
    float*       out    = (float*)d_out;

    const int T = in_sizes[0] / D_IN;   // 8192

    const size_t nwords = (size_t)D_OUT * D_IN / 4;
    pack_w_kernel<<<(int)((nwords + 255) / 256), 256>>>(w32);
    quant_kernel<<<T, 256>>>(x);

    static bool attr_set = false;
    if (!attr_set) {
        cudaFuncSetAttribute(gemm_i8_kernel,
                             cudaFuncAttributeMaxDynamicSharedMemorySize, SMEM_TOTAL);
        attr_set = true;
    }
    dim3 grid(D_OUT / BN, T / BM);      // (32, 64)
    gemm_i8_kernel<<<grid, 256, SMEM_TOTAL>>>(wscale, bias, out);
}

// round 5
// speedup vs baseline: 1.3458x; 1.0274x over previous
#include <cuda_runtime.h>
#include <cstdint>

// Shapes fixed by setup_inputs: x [4,2048,4096] f32, W [4096,4096] int8
// (delivered by harness as int32), wscale [4096] f32, bias [4096] f32.
#define D_IN  4096
#define D_OUT 4096
#define MAX_T 8192

// Scratch (allocation-free rule: __device__ globals)
__device__ int8_t g_xq[(size_t)MAX_T * D_IN];
__device__ float  g_xscale[MAX_T];
__device__ int8_t g_wq[(size_t)D_OUT * D_IN];

// ===========================================================================
// Helpers
// ===========================================================================
__device__ __forceinline__ uint32_t smem_u32(const void* p) {
    uint32_t a;
    asm("{ .reg .u64 t; cvta.to.shared.u64 t, %1; cvt.u32.u64 %0, t; }"
        : "=r"(a) : "l"(p));
    return a;
}
#define CP_ASYNC16(dst, src) \
    asm volatile("cp.async.cg.shared.global [%0], [%1], 16;" \
                 :: "r"(dst), "l"(src) : "memory")
#define CP_COMMIT() asm volatile("cp.async.commit_group;" ::: "memory")
#define CP_WAIT(n)  asm volatile("cp.async.wait_group %0;" :: "n"(n) : "memory")
#define CP_WAIT_ALL() asm volatile("cp.async.wait_all;" ::: "memory")

#define LDMATRIX_X4(r0, r1, r2, r3, addr)                                     \
    asm volatile("ldmatrix.sync.aligned.m8n8.x4.shared.b16 {%0,%1,%2,%3}, [%4];" \
                 : "=r"(r0), "=r"(r1), "=r"(r2), "=r"(r3) : "r"(addr))

// int8 tensor-core MMA (sm_80 baseline): D[16x8]s32 += A[16x32]s8 row * B[32x8]s8 col
__device__ __forceinline__ void mma_i8(int* c, const uint32_t* a, const uint32_t* b) {
    asm volatile(
        "mma.sync.aligned.m16n8k32.row.col.s32.s8.s8.s32 "
        "{%0,%1,%2,%3}, {%4,%5,%6,%7}, {%8,%9}, {%0,%1,%2,%3};"
        : "+r"(c[0]), "+r"(c[1]), "+r"(c[2]), "+r"(c[3])
        : "r"(a[0]), "r"(a[1]), "r"(a[2]), "r"(a[3]), "r"(b[0]), "r"(b[1]));
}

// ===========================================================================
// Kernel 0: repack weights int32 -> int8
// ===========================================================================
__global__ __launch_bounds__(256) void pack_w_kernel(const int* __restrict__ w32)
{
    const size_t i = (size_t)blockIdx.x * blockDim.x + threadIdx.x;
    const size_t nwords = (size_t)D_OUT * D_IN / 4;
    if (i >= nwords) return;
    const int4 v = reinterpret_cast<const int4*>(w32)[i];
    reinterpret_cast<int*>(g_wq)[i] =
        (v.x & 0xFF) | ((v.y & 0xFF) << 8) | ((v.z & 0xFF) << 16) | ((v.w & 0xFF) << 24);
}

// ===========================================================================
// Kernel 1: dynamic per-token int8 quantization (one CTA / token)
// ===========================================================================
__global__ __launch_bounds__(256) void quant_kernel(const float* __restrict__ x)
{
    const int t = blockIdx.x;
    const float4* __restrict__ xr = reinterpret_cast<const float4*>(x + (size_t)t * D_IN);

    float4 v[4];
    float amax = 0.0f;
#pragma unroll
    for (int i = 0; i < 4; i++) {
        v[i] = xr[threadIdx.x + i * 256];
        amax = fmaxf(amax, fmaxf(fmaxf(fabsf(v[i].x), fabsf(v[i].y)),
                                 fmaxf(fabsf(v[i].z), fabsf(v[i].w))));
    }
    __shared__ float red[8];
#pragma unroll
    for (int o = 16; o > 0; o >>= 1)
        amax = fmaxf(amax, __shfl_xor_sync(0xffffffffu, amax, o));
    if ((threadIdx.x & 31) == 0) red[threadIdx.x >> 5] = amax;
    __syncthreads();
    float m = red[0];
#pragma unroll
    for (int w = 1; w < 8; w++) m = fmaxf(m, red[w]);

    const float scale = fmaxf(m, 1e-8f) / 127.0f;
    if (threadIdx.x == 0) g_xscale[t] = scale;

    int* __restrict__ outw = reinterpret_cast<int*>(g_xq + (size_t)t * D_IN);
#pragma unroll
    for (int i = 0; i < 4; i++) {
        int q0 = (int)fminf(fmaxf(rintf(v[i].x / scale), -128.0f), 127.0f);
        int q1 = (int)fminf(fmaxf(rintf(v[i].y / scale), -128.0f), 127.0f);
        int q2 = (int)fminf(fmaxf(rintf(v[i].z / scale), -128.0f), 127.0f);
        int q3 = (int)fminf(fmaxf(rintf(v[i].w / scale), -128.0f), 127.0f);
        outw[threadIdx.x + i * 256] = (q0 & 0xFF) | ((q1 & 0xFF) << 8) |
                                      ((q2 & 0xFF) << 16) | ((q3 & 0xFF) << 24);
    }
}

// ===========================================================================
// Kernel 2: int8 GEMM via mma.sync.m16n8k32 (legacy path; tcgen05 rejected by
// the harness's PTX target sm_103).
// CTA tile 128x128x64, 3-stage cp.async pipeline, 256 threads, 2 CTAs/SM.
// Warp grid 4(M) x 2(N); warp tile 32x64; acc[2][8][4] s32 per thread.
// SMEM rows padded to 80B -> bank(row)=20*row%32 distinct per 8-row tile:
// conflict-free ldmatrix wavefronts. One __syncthreads per K-iter.
// ===========================================================================
#define BM 128
#define BN 128
#define BK 64
#define STAGES 3
#define NKB (D_IN / BK)          // 64
#define ROW_B 80                 // padded row stride in bytes
#define A_TILE (BM * ROW_B)      // 10240
#define B_TILE (BN * ROW_B)      // 10240
#define STAGE_B (A_TILE + B_TILE)            // 20480
#define SMEM_TOTAL (STAGES * STAGE_B)        // 61440

__global__ __launch_bounds__(256, 2) void gemm_i8_kernel(
    const float* __restrict__ wscale,
    const float* __restrict__ bias,
    float* __restrict__ out)
{
    extern __shared__ char smem[];
    const uint32_t sbase = smem_u32(smem);

    const int tid  = threadIdx.x;
    const int lane = tid & 31;
    const int g    = lane >> 2;      // group 0..7
    const int tq   = lane & 3;       // quad 0..3
    const int wid  = tid >> 5;
    const int wm   = wid & 3;        // warp M index (0..3)
    const int wn   = wid >> 2;       // warp N index (0..1)

    const int m0 = blockIdx.y * BM;
    const int n0 = blockIdx.x * BN;

    // cp.async mapping: 1024 16B-chunks/stage (A 512 + B 512), 4 per thread
    const int ldrow = tid >> 2;      // 0..63
    const int ldc   = tid & 3;       // 0..3

    int acc[2][8][4];
#pragma unroll
    for (int mt = 0; mt < 2; mt++)
#pragma unroll
        for (int nt = 0; nt < 8; nt++)
#pragma unroll
            for (int r = 0; r < 4; r++) acc[mt][nt][r] = 0;

    auto load_stage = [&](int s, int kb) {
        const uint32_t sa = sbase + s * STAGE_B;
        const uint32_t sb = sa + A_TILE;
        const size_t kcol = (size_t)kb * BK + ldc * 16;
#pragma unroll
        for (int h = 0; h < 2; h++) {
            const int row = ldrow + h * 64;
            CP_ASYNC16(sa + row * ROW_B + ldc * 16,
                       g_xq + (size_t)(m0 + row) * D_IN + kcol);
        }
#pragma unroll
        for (int h = 0; h < 2; h++) {
            const int row = ldrow + h * 64;
            CP_ASYNC16(sb + row * ROW_B + ldc * 16,
                       g_wq + (size_t)(n0 + row) * D_IN + kcol);
        }
    };

    // ---- prologue: fill STAGES-1 stages ----
#pragma unroll
    for (int s = 0; s < STAGES - 1; s++) {
        load_stage(s, s);
        CP_COMMIT();
    }

    // ---- per-lane ldmatrix addresses (stage-relative) ----
    // A x4 (per mt, ks): lanes 0-7 rows+0 b+0 | 8-15 rows+8 b+0
    //                    | 16-23 rows+0 b+16 | 24-31 rows+8 b+16
    const int a_row = wm * 32 + (lane & 7) + ((lane >> 3) & 1) * 8;
    const int a_b16 = (lane >> 4) * 16;
    uint32_t a_lo[2][2];
#pragma unroll
    for (int mt = 0; mt < 2; mt++)
#pragma unroll
        for (int ks = 0; ks < 2; ks++)
            a_lo[mt][ks] = (uint32_t)((a_row + mt * 16) * ROW_B + ks * 32 + a_b16);

    // B x4 (per t=nt/2, ks): lanes 0-7 rows+0 b+0 | 8-15 rows+0 b+16
    //                        | 16-23 rows+8 b+0  | 24-31 rows+8 b+16
    const int b_row = wn * 64 + (lane & 7) + ((lane >> 4) & 1) * 8;
    const int b_b16 = ((lane >> 3) & 1) * 16;
    uint32_t b_lo[4][2];
#pragma unroll
    for (int t = 0; t < 4; t++)
#pragma unroll
        for (int ks = 0; ks < 2; ks++)
            b_lo[t][ks] = (uint32_t)(A_TILE + (b_row + t * 16) * ROW_B + ks * 32 + b_b16);

    // ---- main loop: ONE barrier per iteration ----
#pragma unroll 1
    for (int kb = 0; kb < NKB; kb++) {
        CP_WAIT(STAGES - 2);
        __syncthreads();   // all warps done reading stage (kb+2)%STAGES (iter kb-1)

        const int pf = kb + STAGES - 1;
        if (pf < NKB) load_stage(pf % STAGES, pf);
        CP_COMMIT();

        const uint32_t st = sbase + (kb % STAGES) * STAGE_B;

#pragma unroll
        for (int ks = 0; ks < 2; ks++) {
            uint32_t af[2][4], bf[8][2];
#pragma unroll
            for (int mt = 0; mt < 2; mt++)
                LDMATRIX_X4(af[mt][0], af[mt][1], af[mt][2], af[mt][3],
                            st + a_lo[mt][ks]);
#pragma unroll
            for (int t = 0; t < 4; t++)
                LDMATRIX_X4(bf[2 * t][0], bf[2 * t][1], bf[2 * t + 1][0],
                            bf[2 * t + 1][1], st + b_lo[t][ks]);
#pragma unroll
            for (int mt = 0; mt < 2; mt++)
#pragma unroll
                for (int nt = 0; nt < 8; nt++)
                    mma_i8(acc[mt][nt], af[mt], bf[nt]);
        }
    }

    // ---- epilogue ----
    CP_WAIT_ALL();
    __syncthreads();
    float* ws_s = reinterpret_cast<float*>(smem);          // 128 floats
    float* bs_s = ws_s + BN;                                // 128 floats
    if (tid < BN) {
        ws_s[tid] = wscale[n0 + tid];
        bs_s[tid] = bias[n0 + tid];
    }
    __syncthreads();

#pragma unroll
    for (int mt = 0; mt < 2; mt++) {
        const int row0 = m0 + wm * 32 + mt * 16 + g;
        const float xs0 = g_xscale[row0];
        const float xs1 = g_xscale[row0 + 8];
        float* __restrict__ o0 = out + (size_t)row0 * D_OUT;
        float* __restrict__ o1 = out + (size_t)(row0 + 8) * D_OUT;
#pragma unroll
        for (int nt = 0; nt < 8; nt++) {
            const int nl = wn * 64 + nt * 8 + tq * 2;
            const float w0 = ws_s[nl], w1 = ws_s[nl + 1];
            const float b0 = bs_s[nl], b1 = bs_s[nl + 1];
            float2 v0, v1;
            v0.x = (float)acc[mt][nt][0] * xs0 * w0 + b0;
            v0.y = (float)acc[mt][nt][1] * xs0 * w1 + b1;
            v1.x = (float)acc[mt][nt][2] * xs1 * w0 + b0;
            v1.y = (float)acc[mt][nt][3] * xs1 * w1 + b1;
            *reinterpret_cast<float2*>(o0 + n0 + nl) = v0;
            *reinterpret_cast<float2*>(o1 + n0 + nl) = v1;
        }
    }
}

// ===========================================================================
extern "C" void kernel_launch(void* const* d_in, const int* in_sizes, int n_in,
                              void* d_out, int out_size)
{
    const float* x      = (const float*)d_in[0];
    const int*   w32    = (const int*)d_in[1];
    const float* wscale = (const float*)d_in[2];
    const float* bias   = (const float*)d_in[3];
    float*       out    = (float*)d_out;

    const int T = in_sizes[0] / D_IN;   // 8192

    const size_t nwords = (size_t)D_OUT * D_IN / 4;
    pack_w_kernel<<<(int)((nwords + 255) / 256), 256>>>(w32);
    quant_kernel<<<T, 256>>>(x);

    static bool attr_set = false;
    if (!attr_set) {
        cudaFuncSetAttribute(gemm_i8_kernel,
                             cudaFuncAttributeMaxDynamicSharedMemorySize, SMEM_TOTAL);
        attr_set = true;
    }
    dim3 grid(D_OUT / BN, T / BM);      // (32, 64)
    gemm_i8_kernel<<<grid, 256, SMEM_TOTAL>>>(wscale, bias, out);
}

// round 6
// speedup vs baseline: 1.8903x; 1.4046x over previous
#include <cuda_runtime.h>
#include <cstdint>

// Shapes fixed by setup_inputs: x [4,2048,4096] f32, W [4096,4096] int8
// (delivered by harness as int32), wscale [4096] f32, bias [4096] f32.
#define D_IN  4096
#define D_OUT 4096
#define MAX_T 8192

// Scratch (allocation-free rule: __device__ globals)
__device__ int8_t g_xq[(size_t)MAX_T * D_IN];
__device__ float  g_xscale[MAX_T];
__device__ int8_t g_wq[(size_t)D_OUT * D_IN];

// ===========================================================================
// Helpers
// ===========================================================================
__device__ __forceinline__ uint32_t smem_u32(const void* p) {
    uint32_t a;
    asm("{ .reg .u64 t; cvta.to.shared.u64 t, %1; cvt.u32.u64 %0, t; }"
        : "=r"(a) : "l"(p));
    return a;
}
#define CP_ASYNC16(dst, src) \
    asm volatile("cp.async.cg.shared.global [%0], [%1], 16;" \
                 :: "r"(dst), "l"(src) : "memory")
#define CP_COMMIT() asm volatile("cp.async.commit_group;" ::: "memory")
#define CP_WAIT(n)  asm volatile("cp.async.wait_group %0;" :: "n"(n) : "memory")
#define CP_WAIT_ALL() asm volatile("cp.async.wait_all;" ::: "memory")

#define LDMATRIX_X4(r0, r1, r2, r3, addr)                                     \
    asm volatile("ldmatrix.sync.aligned.m8n8.x4.shared.b16 {%0,%1,%2,%3}, [%4];" \
                 : "=r"(r0), "=r"(r1), "=r"(r2), "=r"(r3) : "r"(addr))

__device__ __forceinline__ void lds128(int4& v, uint32_t addr) {
    asm volatile("ld.shared.v4.b32 {%0,%1,%2,%3}, [%4];"
                 : "=r"(v.x), "=r"(v.y), "=r"(v.z), "=r"(v.w) : "r"(addr));
}

// int8 tensor-core MMA (sm_80 baseline)
__device__ __forceinline__ void mma_i8(int* c, const uint32_t* a, const uint32_t* b) {
    asm volatile(
        "mma.sync.aligned.m16n8k32.row.col.s32.s8.s8.s32 "
        "{%0,%1,%2,%3}, {%4,%5,%6,%7}, {%8,%9}, {%0,%1,%2,%3};"
        : "+r"(c[0]), "+r"(c[1]), "+r"(c[2]), "+r"(c[3])
        : "r"(a[0]), "r"(a[1]), "r"(a[2]), "r"(a[3]), "r"(b[0]), "r"(b[1]));
}

// ===========================================================================
// Kernel 0: repack weights int32 -> int8
// ===========================================================================
__global__ __launch_bounds__(256) void pack_w_kernel(const int* __restrict__ w32)
{
    const size_t i = (size_t)blockIdx.x * blockDim.x + threadIdx.x;
    const size_t nwords = (size_t)D_OUT * D_IN / 4;
    if (i >= nwords) return;
    const int4 v = reinterpret_cast<const int4*>(w32)[i];
    reinterpret_cast<int*>(g_wq)[i] =
        (v.x & 0xFF) | ((v.y & 0xFF) << 8) | ((v.z & 0xFF) << 16) | ((v.w & 0xFF) << 24);
}

// ===========================================================================
// Kernel 1: dynamic per-token int8 quantization (one CTA / token)
// ===========================================================================
__global__ __launch_bounds__(256) void quant_kernel(const float* __restrict__ x)
{
    const int t = blockIdx.x;
    const float4* __restrict__ xr = reinterpret_cast<const float4*>(x + (size_t)t * D_IN);

    float4 v[4];
    float amax = 0.0f;
#pragma unroll
    for (int i = 0; i < 4; i++) {
        v[i] = xr[threadIdx.x + i * 256];
        amax = fmaxf(amax, fmaxf(fmaxf(fabsf(v[i].x), fabsf(v[i].y)),
                                 fmaxf(fabsf(v[i].z), fabsf(v[i].w))));
    }
    __shared__ float red[8];
#pragma unroll
    for (int o = 16; o > 0; o >>= 1)
        amax = fmaxf(amax, __shfl_xor_sync(0xffffffffu, amax, o));
    if ((threadIdx.x & 31) == 0) red[threadIdx.x >> 5] = amax;
    __syncthreads();
    float m = red[0];
#pragma unroll
    for (int w = 1; w < 8; w++) m = fmaxf(m, red[w]);

    const float scale = fmaxf(m, 1e-8f) / 127.0f;
    if (threadIdx.x == 0) g_xscale[t] = scale;

    int* __restrict__ outw = reinterpret_cast<int*>(g_xq + (size_t)t * D_IN);
#pragma unroll
    for (int i = 0; i < 4; i++) {
        int q0 = (int)fminf(fmaxf(rintf(v[i].x / scale), -128.0f), 127.0f);
        int q1 = (int)fminf(fmaxf(rintf(v[i].y / scale), -128.0f), 127.0f);
        int q2 = (int)fminf(fmaxf(rintf(v[i].z / scale), -128.0f), 127.0f);
        int q3 = (int)fminf(fmaxf(rintf(v[i].w / scale), -128.0f), 127.0f);
        outw[threadIdx.x + i * 256] = (q0 & 0xFF) | ((q1 & 0xFF) << 8) |
                                      ((q2 & 0xFF) << 16) | ((q3 & 0xFF) << 24);
    }
}

// ===========================================================================
// Kernel 2: HYBRID int8 GEMM — tensor pipe (mma.sync) + ALU pipe (dp4a)
// running concurrently in one CTA. The legacy IMMA pipe on sm_103 tops out
// at ~256 MACs/cyc/SM (measured R4/R5); dp4a adds another ~256 on the ALU
// path. CTA tile 128x256: warps 0-7 do cols [0,128) via mma.sync, warps
// 8-15 do cols [128,256) via dp4a. Shared A tile; per-path B tiles.
// 3-stage cp.async pipeline, one barrier per K-iter, 512 threads, 1 CTA/SM.
// ===========================================================================
#define BM 128
#define BN_T 128                 // tensor columns
#define BN_D 128                 // dp4a columns
#define BN (BN_T + BN_D)         // 256
#define BK 64
#define STAGES 3
#define NKB (D_IN / BK)          // 64
#define ROW_B 80                 // padded row stride (tensor tiles)
#define A_TILE (BM * ROW_B)      // 10240
#define BT_TILE (BN_T * ROW_B)   // 10240
#define STAGE_TB (A_TILE + BT_TILE)          // 20480
#define B2_TILE (4 * BN_D * 16)              // 8192 ([kw4][col] int4)
#define OFF_B2 (STAGES * STAGE_TB)           // 61440
#define SMEM_TOTAL (OFF_B2 + STAGES * B2_TILE)   // 86016

__global__ __launch_bounds__(512, 1) void gemm_hybrid_kernel(
    const float* __restrict__ wscale,
    const float* __restrict__ bias,
    float* __restrict__ out)
{
    extern __shared__ char smem[];
    const uint32_t sbase = smem_u32(smem);

    const int tid  = threadIdx.x;
    const int lane = tid & 31;
    const int wid  = tid >> 5;

    const int m0 = blockIdx.y * BM;
    const int n0 = blockIdx.x * BN;

    if (wid < 8) {
        // ===============================================================
        // TENSOR PATH (warps 0-7): cols [n0, n0+128), mma.sync m16n8k32
        // ===============================================================
        const int g  = lane >> 2;
        const int tq = lane & 3;
        const int wm = wid & 3;
        const int wn = wid >> 2;

        const int ldrow = tid >> 2;      // 0..63
        const int ldc   = tid & 3;       // 0..3

        int acc[2][8][4];
#pragma unroll
        for (int mt = 0; mt < 2; mt++)
#pragma unroll
            for (int nt = 0; nt < 8; nt++)
#pragma unroll
                for (int r = 0; r < 4; r++) acc[mt][nt][r] = 0;

        auto load_stage = [&](int s, int kb) {
            const uint32_t sa = sbase + s * STAGE_TB;
            const uint32_t sb = sa + A_TILE;
            const size_t kcol = (size_t)kb * BK + ldc * 16;
#pragma unroll
            for (int h = 0; h < 2; h++) {
                const int row = ldrow + h * 64;
                CP_ASYNC16(sa + row * ROW_B + ldc * 16,
                           g_xq + (size_t)(m0 + row) * D_IN + kcol);
            }
#pragma unroll
            for (int h = 0; h < 2; h++) {
                const int row = ldrow + h * 64;
                CP_ASYNC16(sb + row * ROW_B + ldc * 16,
                           g_wq + (size_t)(n0 + row) * D_IN + kcol);
            }
        };

#pragma unroll
        for (int s = 0; s < STAGES - 1; s++) {
            load_stage(s, s);
            CP_COMMIT();
        }

        const int a_row = wm * 32 + (lane & 7) + ((lane >> 3) & 1) * 8;
        const int a_b16 = (lane >> 4) * 16;
        uint32_t a_lo[2][2];
#pragma unroll
        for (int mt = 0; mt < 2; mt++)
#pragma unroll
            for (int ks = 0; ks < 2; ks++)
                a_lo[mt][ks] = (uint32_t)((a_row + mt * 16) * ROW_B + ks * 32 + a_b16);

        const int b_row = wn * 64 + (lane & 7) + ((lane >> 4) & 1) * 8;
        const int b_b16 = ((lane >> 3) & 1) * 16;
        uint32_t b_lo[4][2];
#pragma unroll
        for (int t = 0; t < 4; t++)
#pragma unroll
            for (int ks = 0; ks < 2; ks++)
                b_lo[t][ks] = (uint32_t)(A_TILE + (b_row + t * 16) * ROW_B + ks * 32 + b_b16);

#pragma unroll 1
        for (int kb = 0; kb < NKB; kb++) {
            CP_WAIT(STAGES - 2);
            __syncthreads();

            const int pf = kb + STAGES - 1;
            if (pf < NKB) load_stage(pf % STAGES, pf);
            CP_COMMIT();

            const uint32_t st = sbase + (kb % STAGES) * STAGE_TB;
#pragma unroll
            for (int ks = 0; ks < 2; ks++) {
                uint32_t af[2][4], bf[8][2];
#pragma unroll
                for (int mt = 0; mt < 2; mt++)
                    LDMATRIX_X4(af[mt][0], af[mt][1], af[mt][2], af[mt][3],
                                st + a_lo[mt][ks]);
#pragma unroll
                for (int t = 0; t < 4; t++)
                    LDMATRIX_X4(bf[2 * t][0], bf[2 * t][1], bf[2 * t + 1][0],
                                bf[2 * t + 1][1], st + b_lo[t][ks]);
#pragma unroll
                for (int mt = 0; mt < 2; mt++)
#pragma unroll
                    for (int nt = 0; nt < 8; nt++)
                        mma_i8(acc[mt][nt], af[mt], bf[nt]);
            }
        }

        // epilogue (tensor)
        CP_WAIT_ALL();
        __syncthreads();
        float* ws_s = reinterpret_cast<float*>(smem);           // 256 floats
        float* bs_s = ws_s + BN;                                 // 256 floats
        if (tid < BN) {
            ws_s[tid] = wscale[n0 + tid];
            bs_s[tid] = bias[n0 + tid];
        }
        __syncthreads();

#pragma unroll
        for (int mt = 0; mt < 2; mt++) {
            const int row0 = m0 + wm * 32 + mt * 16 + g;
            const float xs0 = g_xscale[row0];
            const float xs1 = g_xscale[row0 + 8];
            float* __restrict__ o0 = out + (size_t)row0 * D_OUT;
            float* __restrict__ o1 = out + (size_t)(row0 + 8) * D_OUT;
#pragma unroll
            for (int nt = 0; nt < 8; nt++) {
                const int nl = wn * 64 + nt * 8 + tq * 2;
                const float w0 = ws_s[nl], w1 = ws_s[nl + 1];
                const float b0 = bs_s[nl], b1 = bs_s[nl + 1];
                float2 v0, v1;
                v0.x = (float)acc[mt][nt][0] * xs0 * w0 + b0;
                v0.y = (float)acc[mt][nt][1] * xs0 * w1 + b1;
                v1.x = (float)acc[mt][nt][2] * xs1 * w0 + b0;
                v1.y = (float)acc[mt][nt][3] * xs1 * w1 + b1;
                *reinterpret_cast<float2*>(o0 + n0 + nl) = v0;
                *reinterpret_cast<float2*>(o1 + n0 + nl) = v1;
            }
        }
    } else {
        // ===============================================================
        // DP4A PATH (warps 8-15): cols [n0+128, n0+256)
        // A read from the shared tensor A tile (80B rows, broadcast).
        // B2 tile: [kw4][128 cols] int4 — conflict-free LDS.128.
        // ===============================================================
        const int t2 = tid - 256;         // 0..255
        const int tx = t2 & 15;           // col group
        const int ty = t2 >> 4;           // row group 0..15

        int acc[8][8];
#pragma unroll
        for (int i = 0; i < 8; i++)
#pragma unroll
            for (int j = 0; j < 8; j++) acc[i][j] = 0;

        auto load_stage_d = [&](int s, int kb) {
            const uint32_t b2 = sbase + OFF_B2 + s * B2_TILE;
#pragma unroll
            for (int c = 0; c < 2; c++) {
                const int idx = t2 + c * 256;      // 0..511
                const int col = idx >> 2, kw4 = idx & 3;
                CP_ASYNC16(b2 + (kw4 * BN_D + col) * 16,
                           g_wq + (size_t)(n0 + BN_T + col) * D_IN
                                + (size_t)kb * BK + kw4 * 16);
            }
        };

#pragma unroll
        for (int s = 0; s < STAGES - 1; s++) {
            load_stage_d(s, s);
            CP_COMMIT();
        }

#pragma unroll 1
        for (int kb = 0; kb < NKB; kb++) {
            CP_WAIT(STAGES - 2);
            __syncthreads();

            const int pf = kb + STAGES - 1;
            if (pf < NKB) load_stage_d(pf % STAGES, pf);
            CP_COMMIT();

            const int s = kb % STAGES;
            const uint32_t a_t = sbase + s * STAGE_TB;          // shared A tile
            const uint32_t b2 = sbase + OFF_B2 + s * B2_TILE;

#pragma unroll
            for (int kw4 = 0; kw4 < 4; kw4++) {
                int4 b[8];
#pragma unroll
                for (int j = 0; j < 8; j++)
                    lds128(b[j], b2 + (kw4 * BN_D + j * 16 + tx) * 16);
#pragma unroll
                for (int i = 0; i < 8; i++) {
                    int4 a;
                    lds128(a, a_t + (ty * 8 + i) * ROW_B + kw4 * 16);
#pragma unroll
                    for (int j = 0; j < 8; j++) {
                        acc[i][j] = __dp4a(a.x, b[j].x, acc[i][j]);
                        acc[i][j] = __dp4a(a.y, b[j].y, acc[i][j]);
                        acc[i][j] = __dp4a(a.z, b[j].z, acc[i][j]);
                        acc[i][j] = __dp4a(a.w, b[j].w, acc[i][j]);
                    }
                }
            }
        }

        // epilogue (dp4a)
        CP_WAIT_ALL();
        __syncthreads();
        float* ws_s = reinterpret_cast<float*>(smem);
        float* bs_s = ws_s + BN;
        // ws/bs loaded by tensor-path threads (tid < 256)
        __syncthreads();

#pragma unroll
        for (int i = 0; i < 8; i++) {
            const int m = m0 + ty * 8 + i;
            const float xs = g_xscale[m];
            float* __restrict__ orow = out + (size_t)m * D_OUT;
#pragma unroll
            for (int j = 0; j < 8; j++) {
                const int nl = BN_T + j * 16 + tx;
                orow[n0 + nl] = (float)acc[i][j] * xs * ws_s[nl] + bs_s[nl];
            }
        }
    }
}

// ===========================================================================
extern "C" void kernel_launch(void* const* d_in, const int* in_sizes, int n_in,
                              void* d_out, int out_size)
{
    const float* x      = (const float*)d_in[0];
    const int*   w32    = (const int*)d_in[1];
    const float* wscale = (const float*)d_in[2];
    const float* bias   = (const float*)d_in[3];
    float*       out    = (float*)d_out;

    const int T = in_sizes[0] / D_IN;   // 8192

    const size_t nwords = (size_t)D_OUT * D_IN / 4;
    pack_w_kernel<<<(int)((nwords + 255) / 256), 256>>>(w32);
    quant_kernel<<<T, 256>>>(x);

    static bool attr_set = false;
    if (!attr_set) {
        cudaFuncSetAttribute(gemm_hybrid_kernel,
                             cudaFuncAttributeMaxDynamicSharedMemorySize, SMEM_TOTAL);
        attr_set = true;
    }
    dim3 grid(D_OUT / BN, T / BM);      // (16, 64)
    gemm_hybrid_kernel<<<grid, 512, SMEM_TOTAL>>>(wscale, bias, out);
}